// round 2
// baseline (speedup 1.0000x reference)
#include <cuda_runtime.h>
#include <cstdint>

#define NTOK 8192      // B*S
#define CCH  128       // C
#define HID  256       // 2C
#define SEQ  4096      // S per batch
#define NH   4
#define HD   32

// ---------------- scratch (static device memory, no allocs) ----------------
__device__ float g_qp [NTOK * CCH];
__device__ float g_kp [NTOK * CCH];
__device__ float g_vp [NTOK * CCH];
__device__ float g_x  [NTOK * CCH];
__device__ float g_rs1[NTOK * CCH];
__device__ float g_h  [NTOK * HID];

// ---------------- fast exp2 on the FMA/ALU pipes (no MUFU, no CVT) ---------
__device__ __forceinline__ float fast_exp2(float x) {
    x = fmaxf(x, -125.0f);
    float z = x + 12582912.0f;      // 1.5*2^23 : round-to-nearest integer trick
    float n = z - 12582912.0f;      // n = round(x)
    float f = x - n;                // f in [-0.5, 0.5]
    float p = 1.33335581e-3f;
    p = fmaf(p, f, 9.61812911e-3f);
    p = fmaf(p, f, 5.55041087e-2f);
    p = fmaf(p, f, 2.40226507e-1f);
    p = fmaf(p, f, 6.93147181e-1f);
    p = fmaf(p, f, 1.0f);
    int iz = __float_as_int(z);
    return __int_as_float(__float_as_int(p) + (iz << 23));
}

// ---------------- LayerNorm + [B,C,S] -> [B*S, C] transpose ----------------
// grid (S/32, B), block 256
__global__ __launch_bounds__(256) void ln_transpose_kernel(
    const float* __restrict__ x, const float* __restrict__ gam,
    const float* __restrict__ bet, float* __restrict__ y)
{
    __shared__ float tile[CCH][33];
    __shared__ float rsum[8][32];
    __shared__ float rsq [8][32];
    __shared__ float rmu [32];
    __shared__ float rrs [32];

    const int tid = threadIdx.x;
    const int s0  = blockIdx.x * 32;
    const int bb  = blockIdx.y;

    // coalesced staged load: idx -> c = idx>>5, t = idx&31
    #pragma unroll
    for (int it = 0; it < 16; it++) {
        int idx = tid + it * 256;
        int c = idx >> 5, t = idx & 31;
        tile[c][t] = x[(size_t)bb * CCH * SEQ + (size_t)c * SEQ + s0 + t];
    }
    __syncthreads();

    const int t  = tid & 31;   // token within tile (lane)
    const int gi = tid >> 5;   // warp id = channel group
    float sum = 0.f, sq = 0.f;
    #pragma unroll
    for (int j = 0; j < 16; j++) {
        float v = tile[gi * 16 + j][t];
        sum += v; sq += v * v;
    }
    rsum[gi][t] = sum; rsq[gi][t] = sq;
    __syncthreads();
    if (gi == 0) {
        float s1 = 0.f, s2 = 0.f;
        #pragma unroll
        for (int g = 0; g < 8; g++) { s1 += rsum[g][t]; s2 += rsq[g][t]; }
        float mu  = s1 * (1.0f / CCH);
        float var = s2 * (1.0f / CCH) - mu * mu;
        rmu[t] = mu;
        rrs[t] = rsqrtf(var + 1e-5f);
    }
    __syncthreads();
    float mu = rmu[t], rstd = rrs[t];
    size_t row = ((size_t)bb * SEQ + s0 + t) * CCH;
    #pragma unroll
    for (int j = 0; j < 16; j++) {
        int c = gi * 16 + j;
        y[row + c] = (tile[c][t] - mu) * rstd * gam[c] + bet[c];
    }
}

// ---------------- tiled fp32 GEMM: C[N,M] = A[N,K] @ B[K,M] + bias ----------
// optional LeakyReLU(0.01) and residual add. grid (M/64, N/64), block 256
template <bool LEAKY, bool RES>
__global__ __launch_bounds__(256) void gemm_kernel(
    const float* __restrict__ A, const float* __restrict__ B,
    const float* __restrict__ bias, const float* __restrict__ res,
    float* __restrict__ C, int N, int K, int M)
{
    __shared__ float As[16][68];   // [k][n], padded
    __shared__ float Bs[16][64];   // [k][m]

    const int tid = threadIdx.x;
    const int tx = tid & 15;       // M dir
    const int ty = tid >> 4;       // N dir
    const int n0 = blockIdx.y * 64;
    const int m0 = blockIdx.x * 64;

    float acc[4][4] = {};

    for (int k0 = 0; k0 < K; k0 += 16) {
        {   // A tile: 64 rows x 16 k, float4 per thread, store transposed
            int r  = tid >> 2;
            int kq = tid & 3;
            float4 a = *reinterpret_cast<const float4*>(&A[(size_t)(n0 + r) * K + k0 + kq * 4]);
            As[kq * 4 + 0][r] = a.x;
            As[kq * 4 + 1][r] = a.y;
            As[kq * 4 + 2][r] = a.z;
            As[kq * 4 + 3][r] = a.w;
        }
        {   // B tile: 16 rows x 64 m, coalesced
            int m  = tid & 63;
            int kk = tid >> 6;
            #pragma unroll
            for (int p = 0; p < 4; p++)
                Bs[p * 4 + kk][m] = B[(size_t)(k0 + p * 4 + kk) * M + m0 + m];
        }
        __syncthreads();
        #pragma unroll
        for (int k = 0; k < 16; k++) {
            float4 av = *reinterpret_cast<const float4*>(&As[k][ty * 4]);
            float4 bv = *reinterpret_cast<const float4*>(&Bs[k][tx * 4]);
            float af[4] = {av.x, av.y, av.z, av.w};
            float bf[4] = {bv.x, bv.y, bv.z, bv.w};
            #pragma unroll
            for (int i = 0; i < 4; i++)
                #pragma unroll
                for (int j = 0; j < 4; j++)
                    acc[i][j] = fmaf(af[i], bf[j], acc[i][j]);
        }
        __syncthreads();
    }

    float4 b4 = *reinterpret_cast<const float4*>(&bias[m0 + tx * 4]);
    float bf[4] = {b4.x, b4.y, b4.z, b4.w};
    #pragma unroll
    for (int i = 0; i < 4; i++) {
        int n = n0 + ty * 4 + i;
        float v[4];
        #pragma unroll
        for (int j = 0; j < 4; j++) {
            float t = acc[i][j] + bf[j];
            if (LEAKY) t = fmaxf(t, 0.0f) + 0.01f * fminf(t, 0.0f);
            v[j] = t;
        }
        if (RES) {
            float4 r4 = *reinterpret_cast<const float4*>(&res[(size_t)n * M + m0 + tx * 4]);
            v[0] += r4.x; v[1] += r4.y; v[2] += r4.z; v[3] += r4.w;
        }
        float4 o = {v[0], v[1], v[2], v[3]};
        *reinterpret_cast<float4*>(&C[(size_t)n * M + m0 + tx * 4]) = o;
    }
}

// ---------------- flash attention, 1 thread = 1 query row ------------------
// grid (S/128, B*NH), block 128
__global__ __launch_bounds__(128) void attn_kernel(
    const float* __restrict__ qp, const float* __restrict__ kp,
    const float* __restrict__ vp, float* __restrict__ xo)
{
    constexpr int KT = 32;
    __shared__ float4 Ks[KT][8];
    __shared__ float4 Vs[KT][8];

    const int tid = threadIdx.x;
    const int bh  = blockIdx.y;
    const int bb  = bh >> 2, h = bh & 3;
    const int tok = bb * SEQ + blockIdx.x * 128 + tid;

    // fold log2(e)/sqrt(HD) into q
    const float qkscale = 1.44269504088896f / 5.65685424949238f;

    float4 q4[8];
    const float4* qrow = reinterpret_cast<const float4*>(&qp[(size_t)tok * CCH + h * HD]);
    #pragma unroll
    for (int j = 0; j < 8; j++) {
        q4[j] = qrow[j];
        q4[j].x *= qkscale; q4[j].y *= qkscale; q4[j].z *= qkscale; q4[j].w *= qkscale;
    }

    float4 o4[8];
    #pragma unroll
    for (int j = 0; j < 8; j++) o4[j] = make_float4(0.f, 0.f, 0.f, 0.f);
    float m = -1e30f, l = 0.f;

    for (int kt = 0; kt < SEQ / KT; kt++) {
        __syncthreads();
        #pragma unroll
        for (int i = 0; i < 2; i++) {
            int idx = tid + i * 128;
            int r = idx >> 3, jq = idx & 7;
            size_t goff = ((size_t)(bb * SEQ + kt * KT + r)) * CCH + h * HD + jq * 4;
            Ks[r][jq] = *reinterpret_cast<const float4*>(&kp[goff]);
            Vs[r][jq] = *reinterpret_cast<const float4*>(&vp[goff]);
        }
        __syncthreads();

        float s[KT];
        float tmax = -1e30f;
        #pragma unroll
        for (int kk = 0; kk < KT; kk++) {
            float a = 0.f;
            #pragma unroll
            for (int jj = 0; jj < 8; jj++) {
                float4 kv = Ks[kk][jj];
                a = fmaf(q4[jj].x, kv.x, a);
                a = fmaf(q4[jj].y, kv.y, a);
                a = fmaf(q4[jj].z, kv.z, a);
                a = fmaf(q4[jj].w, kv.w, a);
            }
            s[kk] = a;
            tmax = fmaxf(tmax, a);
        }
        float mnew  = fmaxf(m, tmax);
        float alpha = fast_exp2(m - mnew);
        l *= alpha;
        #pragma unroll
        for (int j = 0; j < 8; j++) {
            o4[j].x *= alpha; o4[j].y *= alpha; o4[j].z *= alpha; o4[j].w *= alpha;
        }
        #pragma unroll
        for (int kk = 0; kk < KT; kk++) {
            float p = fast_exp2(s[kk] - mnew);
            l += p;
            #pragma unroll
            for (int jj = 0; jj < 8; jj++) {
                float4 vv = Vs[kk][jj];
                o4[jj].x = fmaf(p, vv.x, o4[jj].x);
                o4[jj].y = fmaf(p, vv.y, o4[jj].y);
                o4[jj].z = fmaf(p, vv.z, o4[jj].z);
                o4[jj].w = fmaf(p, vv.w, o4[jj].w);
            }
        }
        m = mnew;
    }

    float inv = 1.0f / l;
    float4* out = reinterpret_cast<float4*>(&xo[(size_t)tok * CCH + h * HD]);
    #pragma unroll
    for (int jj = 0; jj < 8; jj++) {
        float4 o = o4[jj];
        o.x *= inv; o.y *= inv; o.z *= inv; o.w *= inv;
        out[jj] = o;
    }
}

// ---------------- [B*S, C] -> [B, C, S] output transpose -------------------
// grid (S/32, C/32, B), block (32, 8)
__global__ __launch_bounds__(256) void out_transpose_kernel(
    const float* __restrict__ src, float* __restrict__ dst)
{
    __shared__ float t[32][33];
    const int tx = threadIdx.x, ty = threadIdx.y;
    const int s0 = blockIdx.x * 32;
    const int c0 = blockIdx.y * 32;
    const int bb = blockIdx.z;
    #pragma unroll
    for (int i = ty; i < 32; i += 8)
        t[i][tx] = src[((size_t)bb * SEQ + s0 + i) * CCH + c0 + tx];
    __syncthreads();
    #pragma unroll
    for (int i = ty; i < 32; i += 8)
        dst[(size_t)bb * CCH * SEQ + (size_t)(c0 + i) * SEQ + s0 + tx] = t[tx][i];
}

// ---------------- launch ----------------------------------------------------
static float* sym(const void* symbol) {
    void* p = nullptr;
    cudaGetSymbolAddress(&p, symbol);
    return reinterpret_cast<float*>(p);
}

extern "C" void kernel_launch(void* const* d_in, const int* in_sizes, int n_in,
                              void* d_out, int out_size)
{
    const float* q = (const float*)d_in[0];
    const float* k = (const float*)d_in[1];
    const float* v = (const float*)d_in[2];
    const float* ln_g[3]  = {(const float*)d_in[3],  (const float*)d_in[9],  (const float*)d_in[15]};
    const float* ln_b[3]  = {(const float*)d_in[4],  (const float*)d_in[10], (const float*)d_in[16]};
    const float* w1[3]    = {(const float*)d_in[5],  (const float*)d_in[11], (const float*)d_in[17]};
    const float* b1[3]    = {(const float*)d_in[6],  (const float*)d_in[12], (const float*)d_in[18]};
    const float* w2[3]    = {(const float*)d_in[7],  (const float*)d_in[13], (const float*)d_in[19]};
    const float* b2[3]    = {(const float*)d_in[8],  (const float*)d_in[14], (const float*)d_in[20]};
    const float* m1_w1 = (const float*)d_in[21];
    const float* m1_b1 = (const float*)d_in[22];
    const float* m1_w2 = (const float*)d_in[23];
    const float* m1_b2 = (const float*)d_in[24];
    const float* m2_w1 = (const float*)d_in[25];
    const float* m2_b1 = (const float*)d_in[26];
    const float* m2_w2 = (const float*)d_in[27];
    const float* m2_b2 = (const float*)d_in[28];

    float* qp  = sym(g_qp);
    float* kp  = sym(g_kp);
    float* vp  = sym(g_vp);
    float* x   = sym(g_x);
    float* rs1 = sym(g_rs1);
    float* hb  = sym(g_h);

    const float* inp[3] = {q, k, v};
    float* prj[3] = {qp, kp, vp};

    dim3 g1(HID / 64, NTOK / 64);   // (4, 128)
    dim3 g2(CCH / 64, NTOK / 64);   // (2, 128)

    for (int p = 0; p < 3; p++) {
        ln_transpose_kernel<<<dim3(SEQ / 32, 2), 256>>>(inp[p], ln_g[p], ln_b[p], x);
        gemm_kernel<true,  false><<<g1, 256>>>(x,  w1[p], b1[p], nullptr, hb,     NTOK, CCH, HID);
        gemm_kernel<false, false><<<g2, 256>>>(hb, w2[p], b2[p], nullptr, prj[p], NTOK, HID, CCH);
    }

    attn_kernel<<<dim3(SEQ / 128, 2 * NH), 128>>>(qp, kp, vp, x);

    gemm_kernel<true,  false><<<g1, 256>>>(x,   m1_w1, m1_b1, nullptr, hb,  NTOK, CCH, HID);
    gemm_kernel<false, true ><<<g2, 256>>>(hb,  m1_w2, m1_b2, vp,      rs1, NTOK, HID, CCH);
    gemm_kernel<true,  false><<<g1, 256>>>(rs1, m2_w1, m2_b1, nullptr, hb,  NTOK, CCH, HID);
    gemm_kernel<false, true ><<<g2, 256>>>(hb,  m2_w2, m2_b2, rs1,     qp,  NTOK, HID, CCH);

    out_transpose_kernel<<<dim3(SEQ / 32, CCH / 32, 2), dim3(32, 8)>>>(qp, (float*)d_out);
}

// round 3
// speedup vs baseline: 1.0209x; 1.0209x over previous
#include <cuda_runtime.h>
#include <cstdint>

#define NTOK 8192      // B*S
#define CCH  128       // C
#define HID  256       // 2C
#define SEQ  4096      // S per batch
#define NH   4
#define HD   32

typedef unsigned long long u64;

// ---------------- scratch (static device memory, no allocs) ----------------
__device__ float g_qp [NTOK * CCH];
__device__ float g_kp [NTOK * CCH];
__device__ float g_vp [NTOK * CCH];
__device__ float g_x  [NTOK * CCH];
__device__ float g_rs1[NTOK * CCH];
__device__ float g_h  [NTOK * HID];

// ---------------- packed f32x2 helpers (FFMA2 path, sm_100+) ---------------
__device__ __forceinline__ u64 pk2(float a, float b) {
    u64 r; asm("mov.b64 %0,{%1,%2};" : "=l"(r) : "f"(a), "f"(b)); return r;
}
__device__ __forceinline__ u64 splat2(float a) {
    u64 r; asm("mov.b64 %0,{%1,%1};" : "=l"(r) : "f"(a)); return r;
}
__device__ __forceinline__ float2 upk2(u64 v) {
    float2 f; asm("mov.b64 {%0,%1},%2;" : "=f"(f.x), "=f"(f.y) : "l"(v)); return f;
}
__device__ __forceinline__ u64 fma2_(u64 a, u64 b, u64 c) {
    u64 d; asm("fma.rn.f32x2 %0,%1,%2,%3;" : "=l"(d) : "l"(a), "l"(b), "l"(c)); return d;
}
__device__ __forceinline__ u64 add2_(u64 a, u64 b) {
    u64 d; asm("add.rn.f32x2 %0,%1,%2;" : "=l"(d) : "l"(a), "l"(b)); return d;
}
__device__ __forceinline__ u64 mul2_(u64 a, u64 b) {
    u64 d; asm("mul.rn.f32x2 %0,%1,%2;" : "=l"(d) : "l"(a), "l"(b)); return d;
}

// ---------------- fast exp2 (FMA pipe only, no MUFU) ------------------------
__device__ __forceinline__ float fast_exp2(float x) {
    x = fmaxf(x, -125.0f);
    float z = x + 12582912.0f;
    float n = z - 12582912.0f;
    float f = x - n;
    float p = 1.33335581e-3f;
    p = fmaf(p, f, 9.61812911e-3f);
    p = fmaf(p, f, 5.55041087e-2f);
    p = fmaf(p, f, 2.40226507e-1f);
    p = fmaf(p, f, 6.93147181e-1f);
    p = fmaf(p, f, 1.0f);
    int iz = __float_as_int(z);
    return __int_as_float(__float_as_int(p) + (iz << 23));
}

// packed exp2 for a pair; inputs must already be clamped to [-125, 0]
__device__ __forceinline__ u64 pexp2_(u64 x) {
    const u64 MG  = splat2(12582912.0f);
    const u64 NMG = splat2(-12582912.0f);
    const u64 N1  = splat2(-1.0f);
    u64 z = add2_(x, MG);
    u64 n = add2_(z, NMG);
    u64 f = fma2_(n, N1, x);           // f = x - n
    u64 p = splat2(1.33335581e-3f);
    p = fma2_(p, f, splat2(9.61812911e-3f));
    p = fma2_(p, f, splat2(5.55041087e-2f));
    p = fma2_(p, f, splat2(2.40226507e-1f));
    p = fma2_(p, f, splat2(6.93147181e-1f));
    p = fma2_(p, f, splat2(1.0f));
    float2 zf = upk2(z), pf = upk2(p);
    int r0 = __float_as_int(pf.x) + (__float_as_int(zf.x) << 23);
    int r1 = __float_as_int(pf.y) + (__float_as_int(zf.y) << 23);
    return pk2(__int_as_float(r0), __int_as_float(r1));
}

// ---------------- LayerNorm + [B,C,S] -> [B*S, C] transpose ----------------
// grid (SEQ/16, B), block 256 (8 warps x 2 tokens each)
__global__ __launch_bounds__(256) void ln_transpose_kernel(
    const float* __restrict__ x, const float* __restrict__ gam,
    const float* __restrict__ bet, float* __restrict__ y)
{
    __shared__ float tile[CCH][17];
    const int tid = threadIdx.x;
    const int s0  = blockIdx.x * 16;
    const int bb  = blockIdx.y;

    #pragma unroll
    for (int it = 0; it < 8; it++) {
        int idx = tid + it * 256;
        int c = idx >> 4, t = idx & 15;
        tile[c][t] = x[(size_t)bb * CCH * SEQ + (size_t)c * SEQ + s0 + t];
    }
    __syncthreads();

    const int w = tid >> 5, lane = tid & 31;
    #pragma unroll
    for (int rep = 0; rep < 2; rep++) {
        int t = w * 2 + rep;
        float sum = 0.f, sq = 0.f;
        #pragma unroll
        for (int j = 0; j < 4; j++) {
            float v = tile[lane + 32 * j][t];
            sum += v; sq += v * v;
        }
        #pragma unroll
        for (int off = 16; off > 0; off >>= 1) {
            sum += __shfl_xor_sync(0xffffffffu, sum, off);
            sq  += __shfl_xor_sync(0xffffffffu, sq,  off);
        }
        float mu   = sum * (1.0f / CCH);
        float var  = sq * (1.0f / CCH) - mu * mu;
        float rstd = rsqrtf(var + 1e-5f);
        size_t row = ((size_t)bb * SEQ + s0 + t) * CCH;
        #pragma unroll
        for (int j = 0; j < 4; j++) {
            int c = lane + 32 * j;
            y[row + c] = (tile[c][t] - mu) * rstd * gam[c] + bet[c];
        }
    }
}

// ---------------- tiled fp32x2 GEMM: C[N,M] = A[N,K] @ B[K,M] + bias --------
// block tile 128(N) x 64(M), K-step 16. 256 threads, micro 8x4 (paired rows).
// grid (M/64, N/128)
template <bool LEAKY, bool RES, bool TRANS>
__global__ __launch_bounds__(256) void gemm_kernel(
    const float* __restrict__ A, const float* __restrict__ B,
    const float* __restrict__ bias, const float* __restrict__ res,
    float* __restrict__ C, int N, int K, int M)
{
    __shared__ float As[16][132];    // [k][row], padded (132*4B = 33*16B)
    __shared__ u64   Bsd[16][64];    // [k][col] duplicated pairs

    const int tid = threadIdx.x;
    const int tx = tid & 15;         // col group (4 cols)
    const int ty = tid >> 4;         // row group (8 rows)
    const int n0 = blockIdx.y * 128;
    const int m0 = blockIdx.x * 64;

    // gmem staging indices
    const int ar  = tid >> 2;        // A: row for f4 idx tid (r of idx)
    const int akq = tid & 3;
    const int bm  = tid & 63;
    const int bk0 = tid >> 6;

    u64 acc[4][4];                   // [col j][row-pair rp]
    #pragma unroll
    for (int j = 0; j < 4; j++)
        #pragma unroll
        for (int rp = 0; rp < 4; rp++) acc[j][rp] = 0ull;

    const int NT = K >> 4;

    // prefetch tile 0
    float4 a0f = *reinterpret_cast<const float4*>(&A[(size_t)(n0 + ar) * K + akq * 4]);
    float4 a1f = *reinterpret_cast<const float4*>(&A[(size_t)(n0 + ar + 64) * K + akq * 4]);
    float bf[4];
    #pragma unroll
    for (int p = 0; p < 4; p++)
        bf[p] = B[(size_t)(p * 4 + bk0) * M + m0 + bm];

    for (int kt = 0; kt < NT; kt++) {
        __syncthreads();
        // store staged tile
        As[akq * 4 + 0][ar] = a0f.x;  As[akq * 4 + 1][ar] = a0f.y;
        As[akq * 4 + 2][ar] = a0f.z;  As[akq * 4 + 3][ar] = a0f.w;
        As[akq * 4 + 0][ar + 64] = a1f.x;  As[akq * 4 + 1][ar + 64] = a1f.y;
        As[akq * 4 + 2][ar + 64] = a1f.z;  As[akq * 4 + 3][ar + 64] = a1f.w;
        #pragma unroll
        for (int p = 0; p < 4; p++)
            Bsd[p * 4 + bk0][bm] = splat2(bf[p]);
        __syncthreads();

        // prefetch next tile
        if (kt + 1 < NT) {
            int k0 = (kt + 1) * 16;
            a0f = *reinterpret_cast<const float4*>(&A[(size_t)(n0 + ar) * K + k0 + akq * 4]);
            a1f = *reinterpret_cast<const float4*>(&A[(size_t)(n0 + ar + 64) * K + k0 + akq * 4]);
            #pragma unroll
            for (int p = 0; p < 4; p++)
                bf[p] = B[(size_t)(k0 + p * 4 + bk0) * M + m0 + bm];
        }

        #pragma unroll
        for (int k = 0; k < 16; k++) {
            const ulonglong2* ap = reinterpret_cast<const ulonglong2*>(&As[k][ty * 8]);
            ulonglong2 av0 = ap[0], av1 = ap[1];
            const ulonglong2* bp = reinterpret_cast<const ulonglong2*>(&Bsd[k][tx * 4]);
            ulonglong2 bv0 = bp[0], bv1 = bp[1];
            u64 ar_[4] = {av0.x, av0.y, av1.x, av1.y};
            u64 bc_[4] = {bv0.x, bv0.y, bv1.x, bv1.y};
            #pragma unroll
            for (int j = 0; j < 4; j++)
                #pragma unroll
                for (int rp = 0; rp < 4; rp++)
                    acc[j][rp] = fma2_(ar_[rp], bc_[j], acc[j][rp]);
        }
    }

    // epilogue
    float4 b4 = *reinterpret_cast<const float4*>(&bias[m0 + tx * 4]);
    float bb_[4] = {b4.x, b4.y, b4.z, b4.w};
    float v[8][4];
    #pragma unroll
    for (int j = 0; j < 4; j++)
        #pragma unroll
        for (int rp = 0; rp < 4; rp++) {
            float2 f = upk2(acc[j][rp]);
            v[2 * rp + 0][j] = f.x;
            v[2 * rp + 1][j] = f.y;
        }
    #pragma unroll
    for (int r = 0; r < 8; r++) {
        int n = n0 + ty * 8 + r;
        #pragma unroll
        for (int j = 0; j < 4; j++) {
            float t = v[r][j] + bb_[j];
            if (LEAKY) t = fmaxf(t, 0.0f) + 0.01f * fminf(t, 0.0f);
            v[r][j] = t;
        }
        if (RES) {
            float4 r4 = *reinterpret_cast<const float4*>(&res[(size_t)n * M + m0 + tx * 4]);
            v[r][0] += r4.x; v[r][1] += r4.y; v[r][2] += r4.z; v[r][3] += r4.w;
        }
    }
    if (!TRANS) {
        #pragma unroll
        for (int r = 0; r < 8; r++) {
            int n = n0 + ty * 8 + r;
            float4 o = {v[r][0], v[r][1], v[r][2], v[r][3]};
            *reinterpret_cast<float4*>(&C[(size_t)n * M + m0 + tx * 4]) = o;
        }
    } else {
        // write [B, C, S]: n -> (b = n>>12, s = n&4095), channel c = m0+tx*4+j
        int nb = n0 + ty * 8;
        int b  = nb >> 12;
        int s  = nb & (SEQ - 1);
        #pragma unroll
        for (int j = 0; j < 4; j++) {
            int c = m0 + tx * 4 + j;
            float* dst = C + (size_t)b * CCH * SEQ + (size_t)c * SEQ + s;
            float4 o0 = {v[0][j], v[1][j], v[2][j], v[3][j]};
            float4 o1 = {v[4][j], v[5][j], v[6][j], v[7][j]};
            *reinterpret_cast<float4*>(dst)     = o0;
            *reinterpret_cast<float4*>(dst + 4) = o1;
        }
    }
}

// ---------------- flash attention, split-K by 2, packed f32x2 ---------------
// block 256: tid<128 -> keys [0,2048), tid>=128 -> keys [2048,4096)
// grid (SEQ/128, B*NH)
#define KT 16
__global__ __launch_bounds__(256, 2) void attn_kernel(
    const float* __restrict__ qp, const float* __restrict__ kp,
    const float* __restrict__ vp, float* __restrict__ xo)
{
    __shared__ ulonglong2 KVs[2][2 * KT][8];   // [K/V][row][jj] : 8KB
    __shared__ float combo[128][33];           // split-1 partials (o, l)
    __shared__ float combm[128];               // split-1 max

    const int tid  = threadIdx.x;
    const int half = tid >> 7;
    const int qi   = tid & 127;
    const int bh   = blockIdx.y;
    const int bb   = bh >> 2, h = bh & 3;
    const int tok  = bb * SEQ + blockIdx.x * 128 + qi;

    const float qkscale = 1.44269504088896f / 5.65685424949238f;  // log2e/sqrt(32)
    const u64 qs2 = splat2(qkscale);

    u64 qq[16];
    const ulonglong2* qr = reinterpret_cast<const ulonglong2*>(qp + (size_t)tok * CCH + h * HD);
    #pragma unroll
    for (int jj = 0; jj < 8; jj++) {
        ulonglong2 t = qr[jj];
        qq[2 * jj]     = mul2_(t.x, qs2);
        qq[2 * jj + 1] = mul2_(t.y, qs2);
    }

    u64 o2[16];
    #pragma unroll
    for (int jj = 0; jj < 16; jj++) o2[jj] = 0ull;
    float m = -1e30f;
    u64 l2 = 0ull;

    const int rbase = half * KT;
    const int NTILE = (SEQ / 2) / KT;   // 128

    // prefetch tile 0 (2 ull2 per thread)
    ulonglong2 pre[2];
    #pragma unroll
    for (int i = 0; i < 2; i++) {
        int id2 = tid + i * 256;
        int a   = id2 >> 8;
        int rem = id2 & 255;
        int row = rem >> 3;
        int jj  = rem & 7;
        int key = bb * SEQ + (row >> 4) * (SEQ / 2) + (row & 15);
        const float* src = a ? vp : kp;
        pre[i] = reinterpret_cast<const ulonglong2*>(src + (size_t)key * CCH + h * HD)[jj];
    }

    for (int kt = 0; kt < NTILE; kt++) {
        __syncthreads();
        #pragma unroll
        for (int i = 0; i < 2; i++) {
            int id2 = tid + i * 256;
            int a   = id2 >> 8;
            int rem = id2 & 255;
            KVs[a][rem >> 3][rem & 7] = pre[i];
        }
        __syncthreads();

        if (kt + 1 < NTILE) {
            #pragma unroll
            for (int i = 0; i < 2; i++) {
                int id2 = tid + i * 256;
                int a   = id2 >> 8;
                int rem = id2 & 255;
                int row = rem >> 3;
                int jj  = rem & 7;
                int key = bb * SEQ + (row >> 4) * (SEQ / 2) + (kt + 1) * KT + (row & 15);
                const float* src = a ? vp : kp;
                pre[i] = reinterpret_cast<const ulonglong2*>(src + (size_t)key * CCH + h * HD)[jj];
            }
        }

        float sc[KT];
        float tmax = -1e30f;
        #pragma unroll
        for (int kk = 0; kk < KT; kk++) {
            u64 a0 = 0ull, a1 = 0ull;
            #pragma unroll
            for (int jj = 0; jj < 8; jj++) {
                ulonglong2 kv = KVs[0][rbase + kk][jj];
                a0 = fma2_(qq[2 * jj],     kv.x, a0);
                a1 = fma2_(qq[2 * jj + 1], kv.y, a1);
            }
            float2 af = upk2(add2_(a0, a1));
            sc[kk] = af.x + af.y;
            tmax = fmaxf(tmax, sc[kk]);
        }

        float mnew  = fmaxf(m, tmax);
        float alpha = fast_exp2(m - mnew);
        u64 al2 = splat2(alpha);
        l2 = mul2_(l2, al2);
        #pragma unroll
        for (int jj = 0; jj < 16; jj++) o2[jj] = mul2_(o2[jj], al2);

        #pragma unroll
        for (int k2 = 0; k2 < KT / 2; k2++) {
            float x0 = fmaxf(sc[2 * k2]     - mnew, -125.0f);
            float x1 = fmaxf(sc[2 * k2 + 1] - mnew, -125.0f);
            u64 e2 = pexp2_(pk2(x0, x1));
            l2 = add2_(l2, e2);
            float2 pf = upk2(e2);
            u64 p0 = splat2(pf.x), p1 = splat2(pf.y);
            #pragma unroll
            for (int jj = 0; jj < 8; jj++) {
                ulonglong2 v0 = KVs[1][rbase + 2 * k2][jj];
                ulonglong2 v1 = KVs[1][rbase + 2 * k2 + 1][jj];
                o2[2 * jj]     = fma2_(p0, v0.x, o2[2 * jj]);
                o2[2 * jj + 1] = fma2_(p0, v0.y, o2[2 * jj + 1]);
                o2[2 * jj]     = fma2_(p1, v1.x, o2[2 * jj]);
                o2[2 * jj + 1] = fma2_(p1, v1.y, o2[2 * jj + 1]);
            }
        }
        m = mnew;
    }

    float2 lf = upk2(l2);
    float lsum = lf.x + lf.y;

    __syncthreads();
    if (half == 1) {
        #pragma unroll
        for (int jj = 0; jj < 16; jj++) {
            float2 f = upk2(o2[jj]);
            combo[qi][2 * jj]     = f.x;
            combo[qi][2 * jj + 1] = f.y;
        }
        combo[qi][32] = lsum;
        combm[qi] = m;
    }
    __syncthreads();
    if (half == 0) {
        float m1 = combm[qi], l1 = combo[qi][32];
        float Mx = fmaxf(m, m1);
        float a0 = fast_exp2(m - Mx), a1 = fast_exp2(m1 - Mx);
        float L  = lsum * a0 + l1 * a1;
        float inv = 1.0f / L;
        float c0 = a0 * inv, c1 = a1 * inv;
        float4* outp = reinterpret_cast<float4*>(xo + (size_t)tok * CCH + h * HD);
        #pragma unroll
        for (int jq = 0; jq < 8; jq++) {
            float2 f0 = upk2(o2[2 * jq]);
            float2 f1 = upk2(o2[2 * jq + 1]);
            float4 o;
            o.x = f0.x * c0 + combo[qi][4 * jq + 0] * c1;
            o.y = f0.y * c0 + combo[qi][4 * jq + 1] * c1;
            o.z = f1.x * c0 + combo[qi][4 * jq + 2] * c1;
            o.w = f1.y * c0 + combo[qi][4 * jq + 3] * c1;
            outp[jq] = o;
        }
    }
}

// ---------------- launch ----------------------------------------------------
static float* sym(const void* symbol) {
    void* p = nullptr;
    cudaGetSymbolAddress(&p, symbol);
    return reinterpret_cast<float*>(p);
}

extern "C" void kernel_launch(void* const* d_in, const int* in_sizes, int n_in,
                              void* d_out, int out_size)
{
    const float* q = (const float*)d_in[0];
    const float* k = (const float*)d_in[1];
    const float* v = (const float*)d_in[2];
    const float* ln_g[3]  = {(const float*)d_in[3],  (const float*)d_in[9],  (const float*)d_in[15]};
    const float* ln_b[3]  = {(const float*)d_in[4],  (const float*)d_in[10], (const float*)d_in[16]};
    const float* w1[3]    = {(const float*)d_in[5],  (const float*)d_in[11], (const float*)d_in[17]};
    const float* b1[3]    = {(const float*)d_in[6],  (const float*)d_in[12], (const float*)d_in[18]};
    const float* w2[3]    = {(const float*)d_in[7],  (const float*)d_in[13], (const float*)d_in[19]};
    const float* b2[3]    = {(const float*)d_in[8],  (const float*)d_in[14], (const float*)d_in[20]};
    const float* m1_w1 = (const float*)d_in[21];
    const float* m1_b1 = (const float*)d_in[22];
    const float* m1_w2 = (const float*)d_in[23];
    const float* m1_b2 = (const float*)d_in[24];
    const float* m2_w1 = (const float*)d_in[25];
    const float* m2_b1 = (const float*)d_in[26];
    const float* m2_w2 = (const float*)d_in[27];
    const float* m2_b2 = (const float*)d_in[28];

    float* qp  = sym(g_qp);
    float* kp  = sym(g_kp);
    float* vp  = sym(g_vp);
    float* x   = sym(g_x);
    float* rs1 = sym(g_rs1);
    float* hb  = sym(g_h);

    const float* inp[3] = {q, k, v};
    float* prj[3] = {qp, kp, vp};

    dim3 g1(HID / 64, NTOK / 128);   // (4, 64)
    dim3 g2(CCH / 64, NTOK / 128);   // (2, 64)

    for (int p = 0; p < 3; p++) {
        ln_transpose_kernel<<<dim3(SEQ / 16, 2), 256>>>(inp[p], ln_g[p], ln_b[p], x);
        gemm_kernel<true,  false, false><<<g1, 256>>>(x,  w1[p], b1[p], nullptr, hb,     NTOK, CCH, HID);
        gemm_kernel<false, false, false><<<g2, 256>>>(hb, w2[p], b2[p], nullptr, prj[p], NTOK, HID, CCH);
    }

    attn_kernel<<<dim3(SEQ / 128, 2 * NH), 256>>>(qp, kp, vp, x);

    gemm_kernel<true,  false, false><<<g1, 256>>>(x,   m1_w1, m1_b1, nullptr, hb,  NTOK, CCH, HID);
    gemm_kernel<false, true,  false><<<g2, 256>>>(hb,  m1_w2, m1_b2, vp,      rs1, NTOK, HID, CCH);
    gemm_kernel<true,  false, false><<<g1, 256>>>(rs1, m2_w1, m2_b1, nullptr, hb,  NTOK, CCH, HID);
    gemm_kernel<false, true,  true ><<<g2, 256>>>(hb,  m2_w2, m2_b2, rs1, (float*)d_out, NTOK, HID, CCH);
}

// round 4
// speedup vs baseline: 2.1476x; 2.1036x over previous
#include <cuda_runtime.h>
#include <cuda_bf16.h>
#include <cstdint>

#define NTOK 8192      // B*S
#define CCH  128       // C
#define HID  256       // 2C
#define SEQ  4096      // S per batch
#define NH   4
#define HD   32

typedef unsigned int u32;
typedef unsigned long long u64;

// ---------------- scratch (static device memory, no allocs) ----------------
__device__ float g_qp [NTOK * CCH];
__device__ float g_kp [NTOK * CCH];
__device__ float g_vp [NTOK * CCH];
__device__ float g_x  [NTOK * CCH];
__device__ float g_rs1[NTOK * CCH];
__device__ float g_h  [NTOK * HID];

// ---------------- packed f32x2 helpers (used by GEMM) ----------------------
__device__ __forceinline__ u64 splat2(float a) {
    u64 r; asm("mov.b64 %0,{%1,%1};" : "=l"(r) : "f"(a)); return r;
}
__device__ __forceinline__ float2 upk2(u64 v) {
    float2 f; asm("mov.b64 {%0,%1},%2;" : "=f"(f.x), "=f"(f.y) : "l"(v)); return f;
}
__device__ __forceinline__ u64 fma2_(u64 a, u64 b, u64 c) {
    u64 d; asm("fma.rn.f32x2 %0,%1,%2,%3;" : "=l"(d) : "l"(a), "l"(b), "l"(c)); return d;
}

// ---------------- bf16 pack helpers -----------------------------------------
// truncation split-hi: exact upper bf16 bits of (x,y) packed (x->low, y->high)
__device__ __forceinline__ u32 packbf_tr(float x, float y) {
    return (__float_as_uint(y) & 0xffff0000u) | (__float_as_uint(x) >> 16);
}
__device__ __forceinline__ float trhi(float x) {
    return __uint_as_float(__float_as_uint(x) & 0xffff0000u);
}
// round-to-nearest pack (x->low, y->high)
__device__ __forceinline__ u32 packbf_rn(float x, float y) {
    u32 d; asm("cvt.rn.bf16x2.f32 %0,%2,%1;" : "=r"(d) : "f"(x), "f"(y)); return d;
}
__device__ __forceinline__ float exf(float x) {   // MUFU exp2
    float r; asm("ex2.approx.f32 %0,%1;" : "=f"(r) : "f"(x)); return r;
}
__device__ __forceinline__ u32 sptr(const void* p) {
    u32 a; asm("{.reg .u64 t; cvta.to.shared.u64 t,%1; cvt.u32.u64 %0,t;}" : "=r"(a) : "l"(p));
    return a;
}

// ---------------- mma / ldmatrix wrappers -----------------------------------
__device__ __forceinline__ void mma16816(float* c, const u32* a, const u32* b) {
    asm volatile(
        "mma.sync.aligned.m16n8k16.row.col.f32.bf16.bf16.f32 "
        "{%0,%1,%2,%3},{%4,%5,%6,%7},{%8,%9},{%0,%1,%2,%3};"
        : "+f"(c[0]), "+f"(c[1]), "+f"(c[2]), "+f"(c[3])
        : "r"(a[0]), "r"(a[1]), "r"(a[2]), "r"(a[3]), "r"(b[0]), "r"(b[1]));
}
__device__ __forceinline__ void ldsm4(u32& r0, u32& r1, u32& r2, u32& r3, u32 addr) {
    asm volatile("ldmatrix.sync.aligned.m8n8.x4.shared.b16 {%0,%1,%2,%3},[%4];"
                 : "=r"(r0), "=r"(r1), "=r"(r2), "=r"(r3) : "r"(addr));
}
__device__ __forceinline__ void ldsm4t(u32& r0, u32& r1, u32& r2, u32& r3, u32 addr) {
    asm volatile("ldmatrix.sync.aligned.m8n8.x4.trans.shared.b16 {%0,%1,%2,%3},[%4];"
                 : "=r"(r0), "=r"(r1), "=r"(r2), "=r"(r3) : "r"(addr));
}

// ---------------- LayerNorm + [B,C,S] -> [B*S, C] transpose ----------------
__global__ __launch_bounds__(256) void ln_transpose_kernel(
    const float* __restrict__ x, const float* __restrict__ gam,
    const float* __restrict__ bet, float* __restrict__ y)
{
    __shared__ float tile[CCH][17];
    const int tid = threadIdx.x;
    const int s0  = blockIdx.x * 16;
    const int bb  = blockIdx.y;

    #pragma unroll
    for (int it = 0; it < 8; it++) {
        int idx = tid + it * 256;
        int c = idx >> 4, t = idx & 15;
        tile[c][t] = x[(size_t)bb * CCH * SEQ + (size_t)c * SEQ + s0 + t];
    }
    __syncthreads();

    const int w = tid >> 5, lane = tid & 31;
    #pragma unroll
    for (int rep = 0; rep < 2; rep++) {
        int t = w * 2 + rep;
        float sum = 0.f, sq = 0.f;
        #pragma unroll
        for (int j = 0; j < 4; j++) {
            float v = tile[lane + 32 * j][t];
            sum += v; sq += v * v;
        }
        #pragma unroll
        for (int off = 16; off > 0; off >>= 1) {
            sum += __shfl_xor_sync(0xffffffffu, sum, off);
            sq  += __shfl_xor_sync(0xffffffffu, sq,  off);
        }
        float mu   = sum * (1.0f / CCH);
        float var  = sq * (1.0f / CCH) - mu * mu;
        float rstd = rsqrtf(var + 1e-5f);
        size_t row = ((size_t)bb * SEQ + s0 + t) * CCH;
        #pragma unroll
        for (int j = 0; j < 4; j++) {
            int c = lane + 32 * j;
            y[row + c] = (tile[c][t] - mu) * rstd * gam[c] + bet[c];
        }
    }
}

// ---------------- tiled fp32 GEMM (unchanged, works) ------------------------
template <bool LEAKY, bool RES, bool TRANS>
__global__ __launch_bounds__(256) void gemm_kernel(
    const float* __restrict__ A, const float* __restrict__ B,
    const float* __restrict__ bias, const float* __restrict__ res,
    float* __restrict__ C, int N, int K, int M)
{
    __shared__ float As[16][132];
    __shared__ u64   Bsd[16][64];

    const int tid = threadIdx.x;
    const int tx = tid & 15;
    const int ty = tid >> 4;
    const int n0 = blockIdx.y * 128;
    const int m0 = blockIdx.x * 64;

    const int ar  = tid >> 2;
    const int akq = tid & 3;
    const int bm  = tid & 63;
    const int bk0 = tid >> 6;

    u64 acc[4][4];
    #pragma unroll
    for (int j = 0; j < 4; j++)
        #pragma unroll
        for (int rp = 0; rp < 4; rp++) acc[j][rp] = 0ull;

    const int NT = K >> 4;

    float4 a0f = *reinterpret_cast<const float4*>(&A[(size_t)(n0 + ar) * K + akq * 4]);
    float4 a1f = *reinterpret_cast<const float4*>(&A[(size_t)(n0 + ar + 64) * K + akq * 4]);
    float bf[4];
    #pragma unroll
    for (int p = 0; p < 4; p++)
        bf[p] = B[(size_t)(p * 4 + bk0) * M + m0 + bm];

    for (int kt = 0; kt < NT; kt++) {
        __syncthreads();
        As[akq * 4 + 0][ar] = a0f.x;  As[akq * 4 + 1][ar] = a0f.y;
        As[akq * 4 + 2][ar] = a0f.z;  As[akq * 4 + 3][ar] = a0f.w;
        As[akq * 4 + 0][ar + 64] = a1f.x;  As[akq * 4 + 1][ar + 64] = a1f.y;
        As[akq * 4 + 2][ar + 64] = a1f.z;  As[akq * 4 + 3][ar + 64] = a1f.w;
        #pragma unroll
        for (int p = 0; p < 4; p++)
            Bsd[p * 4 + bk0][bm] = splat2(bf[p]);
        __syncthreads();

        if (kt + 1 < NT) {
            int k0 = (kt + 1) * 16;
            a0f = *reinterpret_cast<const float4*>(&A[(size_t)(n0 + ar) * K + k0 + akq * 4]);
            a1f = *reinterpret_cast<const float4*>(&A[(size_t)(n0 + ar + 64) * K + k0 + akq * 4]);
            #pragma unroll
            for (int p = 0; p < 4; p++)
                bf[p] = B[(size_t)(k0 + p * 4 + bk0) * M + m0 + bm];
        }

        #pragma unroll
        for (int k = 0; k < 16; k++) {
            const ulonglong2* ap = reinterpret_cast<const ulonglong2*>(&As[k][ty * 8]);
            ulonglong2 av0 = ap[0], av1 = ap[1];
            const ulonglong2* bp = reinterpret_cast<const ulonglong2*>(&Bsd[k][tx * 4]);
            ulonglong2 bv0 = bp[0], bv1 = bp[1];
            u64 ar_[4] = {av0.x, av0.y, av1.x, av1.y};
            u64 bc_[4] = {bv0.x, bv0.y, bv1.x, bv1.y};
            #pragma unroll
            for (int j = 0; j < 4; j++)
                #pragma unroll
                for (int rp = 0; rp < 4; rp++)
                    acc[j][rp] = fma2_(ar_[rp], bc_[j], acc[j][rp]);
        }
    }

    float4 b4 = *reinterpret_cast<const float4*>(&bias[m0 + tx * 4]);
    float bb_[4] = {b4.x, b4.y, b4.z, b4.w};
    float v[8][4];
    #pragma unroll
    for (int j = 0; j < 4; j++)
        #pragma unroll
        for (int rp = 0; rp < 4; rp++) {
            float2 f = upk2(acc[j][rp]);
            v[2 * rp + 0][j] = f.x;
            v[2 * rp + 1][j] = f.y;
        }
    #pragma unroll
    for (int r = 0; r < 8; r++) {
        int n = n0 + ty * 8 + r;
        #pragma unroll
        for (int j = 0; j < 4; j++) {
            float t = v[r][j] + bb_[j];
            if (LEAKY) t = fmaxf(t, 0.0f) + 0.01f * fminf(t, 0.0f);
            v[r][j] = t;
        }
        if (RES) {
            float4 r4 = *reinterpret_cast<const float4*>(&res[(size_t)n * M + m0 + tx * 4]);
            v[r][0] += r4.x; v[r][1] += r4.y; v[r][2] += r4.z; v[r][3] += r4.w;
        }
    }
    if (!TRANS) {
        #pragma unroll
        for (int r = 0; r < 8; r++) {
            int n = n0 + ty * 8 + r;
            float4 o = {v[r][0], v[r][1], v[r][2], v[r][3]};
            *reinterpret_cast<float4*>(&C[(size_t)n * M + m0 + tx * 4]) = o;
        }
    } else {
        int nb = n0 + ty * 8;
        int b  = nb >> 12;
        int s  = nb & (SEQ - 1);
        #pragma unroll
        for (int j = 0; j < 4; j++) {
            int c = m0 + tx * 4 + j;
            float* dst = C + (size_t)b * CCH * SEQ + (size_t)c * SEQ + s;
            float4 o0 = {v[0][j], v[1][j], v[2][j], v[3][j]};
            float4 o1 = {v[4][j], v[5][j], v[6][j], v[7][j]};
            *reinterpret_cast<float4*>(dst)     = o0;
            *reinterpret_cast<float4*>(dst + 4) = o1;
        }
    }
}

// ---------------- FA2 attention on tensor cores (mma.sync bf16) -------------
// block 128 thr (4 warps x 32 q rows), KV tiles of 64 keys, double-buffered.
// QK uses split-bf16 (hi/lo, 3 mma terms); PV uses RN bf16.
#define KVT 64
#define ROWU 20   // padded row: 40 bf16 = 20 u32 = 80B (conflict-free ldmatrix)

__global__ __launch_bounds__(128, 2) void attn_kernel(
    const float* __restrict__ qp, const float* __restrict__ kp,
    const float* __restrict__ vp, float* __restrict__ xo)
{
    __shared__ __align__(16) u32 skhi[2][KVT * ROWU];
    __shared__ __align__(16) u32 sklo[2][KVT * ROWU];
    __shared__ __align__(16) u32 svv [2][KVT * ROWU];

    const int tid  = threadIdx.x;
    const int lane = tid & 31;
    const int w    = tid >> 5;
    const int bh   = blockIdx.y;
    const int bb   = bh >> 2, h = bh & 3;
    const int qbase  = bb * SEQ + blockIdx.x * 128 + w * 32;
    const int kvrow0 = bb * SEQ;

    const float qsc = 1.44269504088896f / 5.65685424949238f;  // log2e/sqrt(32)

    // ---- load Q fragments once (registers), split hi/lo -------------------
    u32 qhiR[2][2][4], qloR[2][2][4];
    #pragma unroll
    for (int mi = 0; mi < 2; mi++) {
        #pragma unroll
        for (int kt = 0; kt < 2; kt++) {
            int r = qbase + mi * 16 + (lane >> 2);
            int c = h * HD + kt * 16 + 2 * (lane & 3);
            float2 v00 = *reinterpret_cast<const float2*>(qp + (size_t)r * CCH + c);
            float2 v10 = *reinterpret_cast<const float2*>(qp + (size_t)(r + 8) * CCH + c);
            float2 v01 = *reinterpret_cast<const float2*>(qp + (size_t)r * CCH + c + 8);
            float2 v11 = *reinterpret_cast<const float2*>(qp + (size_t)(r + 8) * CCH + c + 8);
            v00.x *= qsc; v00.y *= qsc; v10.x *= qsc; v10.y *= qsc;
            v01.x *= qsc; v01.y *= qsc; v11.x *= qsc; v11.y *= qsc;
            qhiR[mi][kt][0] = packbf_tr(v00.x, v00.y);
            qhiR[mi][kt][1] = packbf_tr(v10.x, v10.y);
            qhiR[mi][kt][2] = packbf_tr(v01.x, v01.y);
            qhiR[mi][kt][3] = packbf_tr(v11.x, v11.y);
            qloR[mi][kt][0] = packbf_rn(v00.x - trhi(v00.x), v00.y - trhi(v00.y));
            qloR[mi][kt][1] = packbf_rn(v10.x - trhi(v10.x), v10.y - trhi(v10.y));
            qloR[mi][kt][2] = packbf_rn(v01.x - trhi(v01.x), v01.y - trhi(v01.y));
            qloR[mi][kt][3] = packbf_rn(v11.x - trhi(v11.x), v11.y - trhi(v11.y));
        }
    }

    float o[2][4][4];
    #pragma unroll
    for (int mi = 0; mi < 2; mi++)
        #pragma unroll
        for (int dn = 0; dn < 4; dn++)
            #pragma unroll
            for (int e = 0; e < 4; e++) o[mi][dn][e] = 0.f;
    float mrow[2][2] = {{-1e30f, -1e30f}, {-1e30f, -1e30f}};
    float lrow[2][2] = {{0.f, 0.f}, {0.f, 0.f}};

    // staging indices: 4 float4 per thread per array
    int skey[4], scol[4];
    #pragma unroll
    for (int j = 0; j < 4; j++) {
        int idx = tid + 128 * j;
        skey[j] = idx >> 3;
        scol[j] = idx & 7;
    }

    // ldmatrix lane-address components
    const int g  = lane >> 3;
    const int lr = lane & 7;
    const u32 bKhi0 = sptr(&skhi[0][0]);
    const u32 bKlo0 = sptr(&sklo[0][0]);
    const u32 bV0   = sptr(&svv[0][0]);
    const u32 bufstride = KVT * ROWU * 4;   // bytes per buffer

    // ---- stage tile 0 ------------------------------------------------------
    float4 kreg[4], vreg[4];
    #pragma unroll
    for (int j = 0; j < 4; j++) {
        size_t grow = (size_t)(kvrow0 + skey[j]) * CCH + h * HD + scol[j] * 4;
        kreg[j] = *reinterpret_cast<const float4*>(kp + grow);
        vreg[j] = *reinterpret_cast<const float4*>(vp + grow);
    }
    #pragma unroll
    for (int j = 0; j < 4; j++) {
        int o32 = skey[j] * ROWU + scol[j] * 2;
        float4 kf = kreg[j], vf = vreg[j];
        skhi[0][o32]     = packbf_tr(kf.x, kf.y);
        skhi[0][o32 + 1] = packbf_tr(kf.z, kf.w);
        sklo[0][o32]     = packbf_rn(kf.x - trhi(kf.x), kf.y - trhi(kf.y));
        sklo[0][o32 + 1] = packbf_rn(kf.z - trhi(kf.z), kf.w - trhi(kf.w));
        svv [0][o32]     = packbf_rn(vf.x, vf.y);
        svv [0][o32 + 1] = packbf_rn(vf.z, vf.w);
    }
    __syncthreads();

    const int NT = SEQ / KVT;   // 64
    for (int t = 0; t < NT; t++) {
        const int buf = t & 1;
        const u32 bKhi = bKhi0 + buf * bufstride;
        const u32 bKlo = bKlo0 + buf * bufstride;
        const u32 bV   = bV0   + buf * bufstride;

        // issue gmem loads for next tile (latency hidden under compute)
        if (t + 1 < NT) {
            #pragma unroll
            for (int j = 0; j < 4; j++) {
                size_t grow = (size_t)(kvrow0 + (t + 1) * KVT + skey[j]) * CCH + h * HD + scol[j] * 4;
                kreg[j] = *reinterpret_cast<const float4*>(kp + grow);
                vreg[j] = *reinterpret_cast<const float4*>(vp + grow);
            }
        }

        // ---- QK^T : S[32 x 64] ---------------------------------------------
        float s[2][8][4];
        #pragma unroll
        for (int mi = 0; mi < 2; mi++)
            #pragma unroll
            for (int nt = 0; nt < 8; nt++)
                #pragma unroll
                for (int e = 0; e < 4; e++) s[mi][nt][e] = 0.f;

        #pragma unroll
        for (int kt = 0; kt < 2; kt++) {
            u32 bh_[8][2], bl_[8][2];
            #pragma unroll
            for (int ap = 0; ap < 4; ap++) {
                // key = 16*ap + 8*(g>>1) + lr ; dcol = kt*16 + 8*(g&1)
                u32 off = (u32)((16 * ap + 8 * (g >> 1) + lr) * 80 + (kt * 16 + 8 * (g & 1)) * 2);
                ldsm4(bh_[2 * ap][0], bh_[2 * ap][1], bh_[2 * ap + 1][0], bh_[2 * ap + 1][1], bKhi + off);
                ldsm4(bl_[2 * ap][0], bl_[2 * ap][1], bl_[2 * ap + 1][0], bl_[2 * ap + 1][1], bKlo + off);
            }
            #pragma unroll
            for (int mi = 0; mi < 2; mi++)
                #pragma unroll
                for (int nt = 0; nt < 8; nt++) {
                    mma16816(s[mi][nt], qhiR[mi][kt], bh_[nt]);
                    mma16816(s[mi][nt], qloR[mi][kt], bh_[nt]);
                    mma16816(s[mi][nt], qhiR[mi][kt], bl_[nt]);
                }
        }

        // ---- online softmax --------------------------------------------------
        #pragma unroll
        for (int mi = 0; mi < 2; mi++) {
            float mx0 = -1e30f, mx1 = -1e30f;
            #pragma unroll
            for (int nt = 0; nt < 8; nt++) {
                mx0 = fmaxf(mx0, fmaxf(s[mi][nt][0], s[mi][nt][1]));
                mx1 = fmaxf(mx1, fmaxf(s[mi][nt][2], s[mi][nt][3]));
            }
            mx0 = fmaxf(mx0, __shfl_xor_sync(0xffffffffu, mx0, 1));
            mx0 = fmaxf(mx0, __shfl_xor_sync(0xffffffffu, mx0, 2));
            mx1 = fmaxf(mx1, __shfl_xor_sync(0xffffffffu, mx1, 1));
            mx1 = fmaxf(mx1, __shfl_xor_sync(0xffffffffu, mx1, 2));
            float mn0 = fmaxf(mrow[mi][0], mx0);
            float mn1 = fmaxf(mrow[mi][1], mx1);
            float al0 = exf(mrow[mi][0] - mn0);
            float al1 = exf(mrow[mi][1] - mn1);
            float sum0 = 0.f, sum1 = 0.f;
            #pragma unroll
            for (int nt = 0; nt < 8; nt++) {
                float p0 = exf(s[mi][nt][0] - mn0);
                float p1 = exf(s[mi][nt][1] - mn0);
                float p2 = exf(s[mi][nt][2] - mn1);
                float p3 = exf(s[mi][nt][3] - mn1);
                s[mi][nt][0] = p0; s[mi][nt][1] = p1;
                s[mi][nt][2] = p2; s[mi][nt][3] = p3;
                sum0 += p0 + p1; sum1 += p2 + p3;
            }
            sum0 += __shfl_xor_sync(0xffffffffu, sum0, 1);
            sum0 += __shfl_xor_sync(0xffffffffu, sum0, 2);
            sum1 += __shfl_xor_sync(0xffffffffu, sum1, 1);
            sum1 += __shfl_xor_sync(0xffffffffu, sum1, 2);
            lrow[mi][0] = lrow[mi][0] * al0 + sum0;
            lrow[mi][1] = lrow[mi][1] * al1 + sum1;
            mrow[mi][0] = mn0; mrow[mi][1] = mn1;
            #pragma unroll
            for (int dn = 0; dn < 4; dn++) {
                o[mi][dn][0] *= al0; o[mi][dn][1] *= al0;
                o[mi][dn][2] *= al1; o[mi][dn][3] *= al1;
            }
        }

        // ---- P @ V -----------------------------------------------------------
        #pragma unroll
        for (int kt = 0; kt < 4; kt++) {
            u32 bv[4][2];
            #pragma unroll
            for (int dp = 0; dp < 2; dp++) {
                // key = 16*kt + 8*(g&1) + lr ; dcol = dp*16 + 8*(g>>1)
                u32 off = (u32)((16 * kt + 8 * (g & 1) + lr) * 80 + (dp * 16 + 8 * (g >> 1)) * 2);
                ldsm4t(bv[2 * dp][0], bv[2 * dp][1], bv[2 * dp + 1][0], bv[2 * dp + 1][1], bV + off);
            }
            #pragma unroll
            for (int mi = 0; mi < 2; mi++) {
                u32 pa[4];
                pa[0] = packbf_rn(s[mi][2 * kt][0],     s[mi][2 * kt][1]);
                pa[1] = packbf_rn(s[mi][2 * kt][2],     s[mi][2 * kt][3]);
                pa[2] = packbf_rn(s[mi][2 * kt + 1][0], s[mi][2 * kt + 1][1]);
                pa[3] = packbf_rn(s[mi][2 * kt + 1][2], s[mi][2 * kt + 1][3]);
                #pragma unroll
                for (int dn = 0; dn < 4; dn++)
                    mma16816(o[mi][dn], pa, bv[dn]);
            }
        }

        // ---- stage next tile into other buffer -------------------------------
        if (t + 1 < NT) {
            const int nb = (t + 1) & 1;
            #pragma unroll
            for (int j = 0; j < 4; j++) {
                int o32 = skey[j] * ROWU + scol[j] * 2;
                float4 kf = kreg[j], vf = vreg[j];
                skhi[nb][o32]     = packbf_tr(kf.x, kf.y);
                skhi[nb][o32 + 1] = packbf_tr(kf.z, kf.w);
                sklo[nb][o32]     = packbf_rn(kf.x - trhi(kf.x), kf.y - trhi(kf.y));
                sklo[nb][o32 + 1] = packbf_rn(kf.z - trhi(kf.z), kf.w - trhi(kf.w));
                svv [nb][o32]     = packbf_rn(vf.x, vf.y);
                svv [nb][o32 + 1] = packbf_rn(vf.z, vf.w);
            }
        }
        __syncthreads();
    }

    // ---- finalize & write ----------------------------------------------------
    #pragma unroll
    for (int mi = 0; mi < 2; mi++) {
        float inv0 = 1.0f / lrow[mi][0];
        float inv1 = 1.0f / lrow[mi][1];
        int r = qbase + mi * 16 + (lane >> 2);
        #pragma unroll
        for (int dn = 0; dn < 4; dn++) {
            int c = h * HD + dn * 8 + 2 * (lane & 3);
            float2 o0 = {o[mi][dn][0] * inv0, o[mi][dn][1] * inv0};
            float2 o1 = {o[mi][dn][2] * inv1, o[mi][dn][3] * inv1};
            *reinterpret_cast<float2*>(xo + (size_t)r * CCH + c)       = o0;
            *reinterpret_cast<float2*>(xo + (size_t)(r + 8) * CCH + c) = o1;
        }
    }
}

// ---------------- launch ----------------------------------------------------
static float* sym(const void* symbol) {
    void* p = nullptr;
    cudaGetSymbolAddress(&p, symbol);
    return reinterpret_cast<float*>(p);
}

extern "C" void kernel_launch(void* const* d_in, const int* in_sizes, int n_in,
                              void* d_out, int out_size)
{
    const float* q = (const float*)d_in[0];
    const float* k = (const float*)d_in[1];
    const float* v = (const float*)d_in[2];
    const float* ln_g[3]  = {(const float*)d_in[3],  (const float*)d_in[9],  (const float*)d_in[15]};
    const float* ln_b[3]  = {(const float*)d_in[4],  (const float*)d_in[10], (const float*)d_in[16]};
    const float* w1[3]    = {(const float*)d_in[5],  (const float*)d_in[11], (const float*)d_in[17]};
    const float* b1[3]    = {(const float*)d_in[6],  (const float*)d_in[12], (const float*)d_in[18]};
    const float* w2[3]    = {(const float*)d_in[7],  (const float*)d_in[13], (const float*)d_in[19]};
    const float* b2[3]    = {(const float*)d_in[8],  (const float*)d_in[14], (const float*)d_in[20]};
    const float* m1_w1 = (const float*)d_in[21];
    const float* m1_b1 = (const float*)d_in[22];
    const float* m1_w2 = (const float*)d_in[23];
    const float* m1_b2 = (const float*)d_in[24];
    const float* m2_w1 = (const float*)d_in[25];
    const float* m2_b1 = (const float*)d_in[26];
    const float* m2_w2 = (const float*)d_in[27];
    const float* m2_b2 = (const float*)d_in[28];

    float* qp  = sym(g_qp);
    float* kp  = sym(g_kp);
    float* vp  = sym(g_vp);
    float* x   = sym(g_x);
    float* rs1 = sym(g_rs1);
    float* hb  = sym(g_h);

    const float* inp[3] = {q, k, v};
    float* prj[3] = {qp, kp, vp};

    dim3 g1(HID / 64, NTOK / 128);
    dim3 g2(CCH / 64, NTOK / 128);

    for (int p = 0; p < 3; p++) {
        ln_transpose_kernel<<<dim3(SEQ / 16, 2), 256>>>(inp[p], ln_g[p], ln_b[p], x);
        gemm_kernel<true,  false, false><<<g1, 256>>>(x,  w1[p], b1[p], nullptr, hb,     NTOK, CCH, HID);
        gemm_kernel<false, false, false><<<g2, 256>>>(hb, w2[p], b2[p], nullptr, prj[p], NTOK, HID, CCH);
    }

    attn_kernel<<<dim3(SEQ / 128, 2 * NH), 128>>>(qp, kp, vp, x);

    gemm_kernel<true,  false, false><<<g1, 256>>>(x,   m1_w1, m1_b1, nullptr, hb,  NTOK, CCH, HID);
    gemm_kernel<false, true,  false><<<g2, 256>>>(hb,  m1_w2, m1_b2, vp,      rs1, NTOK, HID, CCH);
    gemm_kernel<true,  false, false><<<g1, 256>>>(rs1, m2_w1, m2_b1, nullptr, hb,  NTOK, CCH, HID);
    gemm_kernel<false, true,  true ><<<g2, 256>>>(hb,  m2_w2, m2_b2, rs1, (float*)d_out, NTOK, HID, CCH);
}

// round 5
// speedup vs baseline: 3.8268x; 1.7818x over previous
#include <cuda_runtime.h>
#include <cuda_bf16.h>
#include <cstdint>

#define NTOK 8192      // B*S
#define CCH  128       // C
#define HID  256       // 2C
#define SEQ  4096      // S per batch
#define NH   4
#define HD   32

typedef unsigned int u32;

// ---------------- scratch (static device memory, no allocs) ----------------
__device__ float g_qp [NTOK * CCH];
__device__ float g_kp [NTOK * CCH];
__device__ float g_vp [NTOK * CCH];
__device__ float g_x  [NTOK * CCH];
__device__ float g_rs1[NTOK * CCH];
__device__ float g_h  [NTOK * HID];

// ---------------- bf16 pack helpers -----------------------------------------
__device__ __forceinline__ u32 packbf_tr(float x, float y) {   // truncation hi
    return (__float_as_uint(y) & 0xffff0000u) | (__float_as_uint(x) >> 16);
}
__device__ __forceinline__ float trhi(float x) {
    return __uint_as_float(__float_as_uint(x) & 0xffff0000u);
}
__device__ __forceinline__ u32 packbf_rn(float x, float y) {   // x->low, y->high
    u32 d; asm("cvt.rn.bf16x2.f32 %0,%2,%1;" : "=r"(d) : "f"(x), "f"(y)); return d;
}
__device__ __forceinline__ float exf(float x) {                // MUFU exp2
    float r; asm("ex2.approx.f32 %0,%1;" : "=f"(r) : "f"(x)); return r;
}
__device__ __forceinline__ u32 sptr(const void* p) {
    u32 a; asm("{.reg .u64 t; cvta.to.shared.u64 t,%1; cvt.u32.u64 %0,t;}" : "=r"(a) : "l"(p));
    return a;
}

// ---------------- mma / ldmatrix wrappers -----------------------------------
__device__ __forceinline__ void mma16816(float* c, const u32* a, const u32* b) {
    asm volatile(
        "mma.sync.aligned.m16n8k16.row.col.f32.bf16.bf16.f32 "
        "{%0,%1,%2,%3},{%4,%5,%6,%7},{%8,%9},{%0,%1,%2,%3};"
        : "+f"(c[0]), "+f"(c[1]), "+f"(c[2]), "+f"(c[3])
        : "r"(a[0]), "r"(a[1]), "r"(a[2]), "r"(a[3]), "r"(b[0]), "r"(b[1]));
}
__device__ __forceinline__ void ldsm4(u32& r0, u32& r1, u32& r2, u32& r3, u32 addr) {
    asm volatile("ldmatrix.sync.aligned.m8n8.x4.shared.b16 {%0,%1,%2,%3},[%4];"
                 : "=r"(r0), "=r"(r1), "=r"(r2), "=r"(r3) : "r"(addr));
}
__device__ __forceinline__ void ldsm4t(u32& r0, u32& r1, u32& r2, u32& r3, u32 addr) {
    asm volatile("ldmatrix.sync.aligned.m8n8.x4.trans.shared.b16 {%0,%1,%2,%3},[%4];"
                 : "=r"(r0), "=r"(r1), "=r"(r2), "=r"(r3) : "r"(addr));
}

// ---------------- LayerNorm + [B,C,S] -> [B*S, C] transpose ----------------
__global__ __launch_bounds__(256) void ln_transpose_kernel(
    const float* __restrict__ x, const float* __restrict__ gam,
    const float* __restrict__ bet, float* __restrict__ y)
{
    __shared__ float tile[CCH][17];
    const int tid = threadIdx.x;
    const int s0  = blockIdx.x * 16;
    const int bb  = blockIdx.y;

    #pragma unroll
    for (int it = 0; it < 8; it++) {
        int idx = tid + it * 256;
        int c = idx >> 4, t = idx & 15;
        tile[c][t] = x[(size_t)bb * CCH * SEQ + (size_t)c * SEQ + s0 + t];
    }
    __syncthreads();

    const int w = tid >> 5, lane = tid & 31;
    #pragma unroll
    for (int rep = 0; rep < 2; rep++) {
        int t = w * 2 + rep;
        float sum = 0.f, sq = 0.f;
        #pragma unroll
        for (int j = 0; j < 4; j++) {
            float v = tile[lane + 32 * j][t];
            sum += v; sq += v * v;
        }
        #pragma unroll
        for (int off = 16; off > 0; off >>= 1) {
            sum += __shfl_xor_sync(0xffffffffu, sum, off);
            sq  += __shfl_xor_sync(0xffffffffu, sq,  off);
        }
        float mu   = sum * (1.0f / CCH);
        float var  = sq * (1.0f / CCH) - mu * mu;
        float rstd = rsqrtf(var + 1e-5f);
        size_t row = ((size_t)bb * SEQ + s0 + t) * CCH;
        #pragma unroll
        for (int j = 0; j < 4; j++) {
            int c = lane + 32 * j;
            y[row + c] = (tile[c][t] - mu) * rstd * gam[c] + bet[c];
        }
    }
}

// ---------------- split-bf16 tensor-core GEMM --------------------------------
// C[N,M] = A[N,K] @ B[K,M] (+bias, LeakyReLU, residual)
// block: 128(N) x 64(M), BK=16, 128 threads (4 warps x [32 rows x 64 cols])
// 3-term split: Ahi*Bhi + Ahi*Blo + Alo*Bhi
#define AROW 12   // A smem row stride in u32 (48B: 16 bf16 + pad)
#define BROW 36   // B smem row stride in u32 (144B: 64 bf16 + pad)

template <bool LEAKY, bool RES>
__global__ __launch_bounds__(128) void gemm_bf16_kernel(
    const float* __restrict__ A, const float* __restrict__ B,
    const float* __restrict__ bias, const float* __restrict__ res,
    float* __restrict__ C, int N, int K, int M)
{
    __shared__ __align__(16) u32 sAhi[2][128 * AROW];
    __shared__ __align__(16) u32 sAlo[2][128 * AROW];
    __shared__ __align__(16) u32 sBhi[2][16 * BROW];
    __shared__ __align__(16) u32 sBlo[2][16 * BROW];

    const int tid  = threadIdx.x;
    const int lane = tid & 31;
    const int w    = tid >> 5;
    const int n0 = blockIdx.y * 128;
    const int m0 = blockIdx.x * 64;

    const int g  = lane >> 3;
    const int lr = lane & 7;

    // staging indices
    int arow[4], acol[4];                    // A: 4 float4/thread (128x16)
    #pragma unroll
    for (int j = 0; j < 4; j++) {
        int idx = tid + 128 * j;
        arow[j] = idx >> 2;
        acol[j] = idx & 3;
    }
    int brow[2], bcol[2];                    // B: 2 float4/thread (16x64)
    #pragma unroll
    for (int j = 0; j < 2; j++) {
        int idx = tid + 128 * j;
        brow[j] = idx >> 4;
        bcol[j] = idx & 15;
    }

    float c[2][8][4];
    #pragma unroll
    for (int mi = 0; mi < 2; mi++)
        #pragma unroll
        for (int nt = 0; nt < 8; nt++)
            #pragma unroll
            for (int e = 0; e < 4; e++) c[mi][nt][e] = 0.f;

    const u32 bA0 = sptr(&sAhi[0][0]);
    const u32 bAl0 = sptr(&sAlo[0][0]);
    const u32 bB0 = sptr(&sBhi[0][0]);
    const u32 bBl0 = sptr(&sBlo[0][0]);
    const u32 abuf = 128 * AROW * 4;
    const u32 bbuf = 16 * BROW * 4;

    const int NT = K >> 4;

    // prefetch tile 0
    float4 af[4], bf4[2];
    #pragma unroll
    for (int j = 0; j < 4; j++)
        af[j] = *reinterpret_cast<const float4*>(&A[(size_t)(n0 + arow[j]) * K + acol[j] * 4]);
    #pragma unroll
    for (int j = 0; j < 2; j++)
        bf4[j] = *reinterpret_cast<const float4*>(&B[(size_t)brow[j] * M + m0 + bcol[j] * 4]);

    // stage into buf 0
    #pragma unroll
    for (int j = 0; j < 4; j++) {
        int o = arow[j] * AROW + acol[j] * 2;
        float4 f = af[j];
        sAhi[0][o]     = packbf_tr(f.x, f.y);
        sAhi[0][o + 1] = packbf_tr(f.z, f.w);
        sAlo[0][o]     = packbf_rn(f.x - trhi(f.x), f.y - trhi(f.y));
        sAlo[0][o + 1] = packbf_rn(f.z - trhi(f.z), f.w - trhi(f.w));
    }
    #pragma unroll
    for (int j = 0; j < 2; j++) {
        int o = brow[j] * BROW + bcol[j] * 2;
        float4 f = bf4[j];
        sBhi[0][o]     = packbf_tr(f.x, f.y);
        sBhi[0][o + 1] = packbf_tr(f.z, f.w);
        sBlo[0][o]     = packbf_rn(f.x - trhi(f.x), f.y - trhi(f.y));
        sBlo[0][o + 1] = packbf_rn(f.z - trhi(f.z), f.w - trhi(f.w));
    }
    __syncthreads();

    for (int t = 0; t < NT; t++) {
        const int buf = t & 1;
        const u32 aH = bA0  + buf * abuf;
        const u32 aL = bAl0 + buf * abuf;
        const u32 bH = bB0  + buf * bbuf;
        const u32 bL = bBl0 + buf * bbuf;

        // prefetch next
        if (t + 1 < NT) {
            int k0 = (t + 1) * 16;
            #pragma unroll
            for (int j = 0; j < 4; j++)
                af[j] = *reinterpret_cast<const float4*>(&A[(size_t)(n0 + arow[j]) * K + k0 + acol[j] * 4]);
            #pragma unroll
            for (int j = 0; j < 2; j++)
                bf4[j] = *reinterpret_cast<const float4*>(&B[(size_t)(k0 + brow[j]) * M + m0 + bcol[j] * 4]);
        }

        // load fragments
        u32 ahi[2][4], alo[2][4];
        #pragma unroll
        for (int mi = 0; mi < 2; mi++) {
            u32 off = (u32)((w * 32 + mi * 16 + (g & 1) * 8 + lr) * 48 + (g >> 1) * 16);
            ldsm4(ahi[mi][0], ahi[mi][1], ahi[mi][2], ahi[mi][3], aH + off);
            ldsm4(alo[mi][0], alo[mi][1], alo[mi][2], alo[mi][3], aL + off);
        }
        u32 bhi[8][2], blo[8][2];
        #pragma unroll
        for (int dp = 0; dp < 4; dp++) {
            u32 off = (u32)((8 * (g & 1) + lr) * 144 + (dp * 16 + 8 * (g >> 1)) * 2);
            ldsm4t(bhi[2 * dp][0], bhi[2 * dp][1], bhi[2 * dp + 1][0], bhi[2 * dp + 1][1], bH + off);
            ldsm4t(blo[2 * dp][0], blo[2 * dp][1], blo[2 * dp + 1][0], blo[2 * dp + 1][1], bL + off);
        }

        #pragma unroll
        for (int mi = 0; mi < 2; mi++)
            #pragma unroll
            for (int nt = 0; nt < 8; nt++) {
                mma16816(c[mi][nt], ahi[mi], bhi[nt]);
                mma16816(c[mi][nt], ahi[mi], blo[nt]);
                mma16816(c[mi][nt], alo[mi], bhi[nt]);
            }

        // stage next tile
        if (t + 1 < NT) {
            const int nb = (t + 1) & 1;
            #pragma unroll
            for (int j = 0; j < 4; j++) {
                int o = arow[j] * AROW + acol[j] * 2;
                float4 f = af[j];
                sAhi[nb][o]     = packbf_tr(f.x, f.y);
                sAhi[nb][o + 1] = packbf_tr(f.z, f.w);
                sAlo[nb][o]     = packbf_rn(f.x - trhi(f.x), f.y - trhi(f.y));
                sAlo[nb][o + 1] = packbf_rn(f.z - trhi(f.z), f.w - trhi(f.w));
            }
            #pragma unroll
            for (int j = 0; j < 2; j++) {
                int o = brow[j] * BROW + bcol[j] * 2;
                float4 f = bf4[j];
                sBhi[nb][o]     = packbf_tr(f.x, f.y);
                sBhi[nb][o + 1] = packbf_tr(f.z, f.w);
                sBlo[nb][o]     = packbf_rn(f.x - trhi(f.x), f.y - trhi(f.y));
                sBlo[nb][o + 1] = packbf_rn(f.z - trhi(f.z), f.w - trhi(f.w));
            }
        }
        __syncthreads();
    }

    // ---- epilogue -----------------------------------------------------------
    #pragma unroll
    for (int mi = 0; mi < 2; mi++) {
        int r0 = n0 + w * 32 + mi * 16 + (lane >> 2);
        #pragma unroll
        for (int nt = 0; nt < 8; nt++) {
            int col = m0 + nt * 8 + (lane & 3) * 2;
            float2 bb = *reinterpret_cast<const float2*>(&bias[col]);
            float v0 = c[mi][nt][0] + bb.x;
            float v1 = c[mi][nt][1] + bb.y;
            float v2 = c[mi][nt][2] + bb.x;
            float v3 = c[mi][nt][3] + bb.y;
            if (LEAKY) {
                v0 = fmaxf(v0, 0.f) + 0.01f * fminf(v0, 0.f);
                v1 = fmaxf(v1, 0.f) + 0.01f * fminf(v1, 0.f);
                v2 = fmaxf(v2, 0.f) + 0.01f * fminf(v2, 0.f);
                v3 = fmaxf(v3, 0.f) + 0.01f * fminf(v3, 0.f);
            }
            if (RES) {
                float2 r4a = *reinterpret_cast<const float2*>(&res[(size_t)r0 * M + col]);
                float2 r4b = *reinterpret_cast<const float2*>(&res[(size_t)(r0 + 8) * M + col]);
                v0 += r4a.x; v1 += r4a.y; v2 += r4b.x; v3 += r4b.y;
            }
            *reinterpret_cast<float2*>(&C[(size_t)r0 * M + col])       = make_float2(v0, v1);
            *reinterpret_cast<float2*>(&C[(size_t)(r0 + 8) * M + col]) = make_float2(v2, v3);
        }
    }
}

// ---------------- FA2 attention on tensor cores (from R4, passing) ----------
#define KVT 64
#define ROWU 20

__global__ __launch_bounds__(128, 2) void attn_kernel(
    const float* __restrict__ qp, const float* __restrict__ kp,
    const float* __restrict__ vp, float* __restrict__ xo)
{
    __shared__ __align__(16) u32 skhi[2][KVT * ROWU];
    __shared__ __align__(16) u32 sklo[2][KVT * ROWU];
    __shared__ __align__(16) u32 svv [2][KVT * ROWU];

    const int tid  = threadIdx.x;
    const int lane = tid & 31;
    const int w    = tid >> 5;
    const int bh   = blockIdx.y;
    const int bb   = bh >> 2, h = bh & 3;
    const int qbase  = bb * SEQ + blockIdx.x * 128 + w * 32;
    const int kvrow0 = bb * SEQ;

    const float qsc = 1.44269504088896f / 5.65685424949238f;

    u32 qhiR[2][2][4], qloR[2][2][4];
    #pragma unroll
    for (int mi = 0; mi < 2; mi++) {
        #pragma unroll
        for (int kt = 0; kt < 2; kt++) {
            int r = qbase + mi * 16 + (lane >> 2);
            int cc = h * HD + kt * 16 + 2 * (lane & 3);
            float2 v00 = *reinterpret_cast<const float2*>(qp + (size_t)r * CCH + cc);
            float2 v10 = *reinterpret_cast<const float2*>(qp + (size_t)(r + 8) * CCH + cc);
            float2 v01 = *reinterpret_cast<const float2*>(qp + (size_t)r * CCH + cc + 8);
            float2 v11 = *reinterpret_cast<const float2*>(qp + (size_t)(r + 8) * CCH + cc + 8);
            v00.x *= qsc; v00.y *= qsc; v10.x *= qsc; v10.y *= qsc;
            v01.x *= qsc; v01.y *= qsc; v11.x *= qsc; v11.y *= qsc;
            qhiR[mi][kt][0] = packbf_tr(v00.x, v00.y);
            qhiR[mi][kt][1] = packbf_tr(v10.x, v10.y);
            qhiR[mi][kt][2] = packbf_tr(v01.x, v01.y);
            qhiR[mi][kt][3] = packbf_tr(v11.x, v11.y);
            qloR[mi][kt][0] = packbf_rn(v00.x - trhi(v00.x), v00.y - trhi(v00.y));
            qloR[mi][kt][1] = packbf_rn(v10.x - trhi(v10.x), v10.y - trhi(v10.y));
            qloR[mi][kt][2] = packbf_rn(v01.x - trhi(v01.x), v01.y - trhi(v01.y));
            qloR[mi][kt][3] = packbf_rn(v11.x - trhi(v11.x), v11.y - trhi(v11.y));
        }
    }

    float o[2][4][4];
    #pragma unroll
    for (int mi = 0; mi < 2; mi++)
        #pragma unroll
        for (int dn = 0; dn < 4; dn++)
            #pragma unroll
            for (int e = 0; e < 4; e++) o[mi][dn][e] = 0.f;
    float mrow[2][2] = {{-1e30f, -1e30f}, {-1e30f, -1e30f}};
    float lrow[2][2] = {{0.f, 0.f}, {0.f, 0.f}};

    int skey[4], scol[4];
    #pragma unroll
    for (int j = 0; j < 4; j++) {
        int idx = tid + 128 * j;
        skey[j] = idx >> 3;
        scol[j] = idx & 7;
    }

    const int g  = lane >> 3;
    const int lr = lane & 7;
    const u32 bKhi0 = sptr(&skhi[0][0]);
    const u32 bKlo0 = sptr(&sklo[0][0]);
    const u32 bV0   = sptr(&svv[0][0]);
    const u32 bufstride = KVT * ROWU * 4;

    float4 kreg[4], vreg[4];
    #pragma unroll
    for (int j = 0; j < 4; j++) {
        size_t grow = (size_t)(kvrow0 + skey[j]) * CCH + h * HD + scol[j] * 4;
        kreg[j] = *reinterpret_cast<const float4*>(kp + grow);
        vreg[j] = *reinterpret_cast<const float4*>(vp + grow);
    }
    #pragma unroll
    for (int j = 0; j < 4; j++) {
        int o32 = skey[j] * ROWU + scol[j] * 2;
        float4 kf = kreg[j], vf = vreg[j];
        skhi[0][o32]     = packbf_tr(kf.x, kf.y);
        skhi[0][o32 + 1] = packbf_tr(kf.z, kf.w);
        sklo[0][o32]     = packbf_rn(kf.x - trhi(kf.x), kf.y - trhi(kf.y));
        sklo[0][o32 + 1] = packbf_rn(kf.z - trhi(kf.z), kf.w - trhi(kf.w));
        svv [0][o32]     = packbf_rn(vf.x, vf.y);
        svv [0][o32 + 1] = packbf_rn(vf.z, vf.w);
    }
    __syncthreads();

    const int NT = SEQ / KVT;
    for (int t = 0; t < NT; t++) {
        const int buf = t & 1;
        const u32 bKhi = bKhi0 + buf * bufstride;
        const u32 bKlo = bKlo0 + buf * bufstride;
        const u32 bV   = bV0   + buf * bufstride;

        if (t + 1 < NT) {
            #pragma unroll
            for (int j = 0; j < 4; j++) {
                size_t grow = (size_t)(kvrow0 + (t + 1) * KVT + skey[j]) * CCH + h * HD + scol[j] * 4;
                kreg[j] = *reinterpret_cast<const float4*>(kp + grow);
                vreg[j] = *reinterpret_cast<const float4*>(vp + grow);
            }
        }

        float s[2][8][4];
        #pragma unroll
        for (int mi = 0; mi < 2; mi++)
            #pragma unroll
            for (int nt = 0; nt < 8; nt++)
                #pragma unroll
                for (int e = 0; e < 4; e++) s[mi][nt][e] = 0.f;

        #pragma unroll
        for (int kt = 0; kt < 2; kt++) {
            u32 bh_[8][2], bl_[8][2];
            #pragma unroll
            for (int ap = 0; ap < 4; ap++) {
                u32 off = (u32)((16 * ap + 8 * (g >> 1) + lr) * 80 + (kt * 16 + 8 * (g & 1)) * 2);
                ldsm4(bh_[2 * ap][0], bh_[2 * ap][1], bh_[2 * ap + 1][0], bh_[2 * ap + 1][1], bKhi + off);
                ldsm4(bl_[2 * ap][0], bl_[2 * ap][1], bl_[2 * ap + 1][0], bl_[2 * ap + 1][1], bKlo + off);
            }
            #pragma unroll
            for (int mi = 0; mi < 2; mi++)
                #pragma unroll
                for (int nt = 0; nt < 8; nt++) {
                    mma16816(s[mi][nt], qhiR[mi][kt], bh_[nt]);
                    mma16816(s[mi][nt], qloR[mi][kt], bh_[nt]);
                    mma16816(s[mi][nt], qhiR[mi][kt], bl_[nt]);
                }
        }

        #pragma unroll
        for (int mi = 0; mi < 2; mi++) {
            float mx0 = -1e30f, mx1 = -1e30f;
            #pragma unroll
            for (int nt = 0; nt < 8; nt++) {
                mx0 = fmaxf(mx0, fmaxf(s[mi][nt][0], s[mi][nt][1]));
                mx1 = fmaxf(mx1, fmaxf(s[mi][nt][2], s[mi][nt][3]));
            }
            mx0 = fmaxf(mx0, __shfl_xor_sync(0xffffffffu, mx0, 1));
            mx0 = fmaxf(mx0, __shfl_xor_sync(0xffffffffu, mx0, 2));
            mx1 = fmaxf(mx1, __shfl_xor_sync(0xffffffffu, mx1, 1));
            mx1 = fmaxf(mx1, __shfl_xor_sync(0xffffffffu, mx1, 2));
            float mn0 = fmaxf(mrow[mi][0], mx0);
            float mn1 = fmaxf(mrow[mi][1], mx1);
            float al0 = exf(mrow[mi][0] - mn0);
            float al1 = exf(mrow[mi][1] - mn1);
            float sum0 = 0.f, sum1 = 0.f;
            #pragma unroll
            for (int nt = 0; nt < 8; nt++) {
                float p0 = exf(s[mi][nt][0] - mn0);
                float p1 = exf(s[mi][nt][1] - mn0);
                float p2 = exf(s[mi][nt][2] - mn1);
                float p3 = exf(s[mi][nt][3] - mn1);
                s[mi][nt][0] = p0; s[mi][nt][1] = p1;
                s[mi][nt][2] = p2; s[mi][nt][3] = p3;
                sum0 += p0 + p1; sum1 += p2 + p3;
            }
            sum0 += __shfl_xor_sync(0xffffffffu, sum0, 1);
            sum0 += __shfl_xor_sync(0xffffffffu, sum0, 2);
            sum1 += __shfl_xor_sync(0xffffffffu, sum1, 1);
            sum1 += __shfl_xor_sync(0xffffffffu, sum1, 2);
            lrow[mi][0] = lrow[mi][0] * al0 + sum0;
            lrow[mi][1] = lrow[mi][1] * al1 + sum1;
            mrow[mi][0] = mn0; mrow[mi][1] = mn1;
            #pragma unroll
            for (int dn = 0; dn < 4; dn++) {
                o[mi][dn][0] *= al0; o[mi][dn][1] *= al0;
                o[mi][dn][2] *= al1; o[mi][dn][3] *= al1;
            }
        }

        #pragma unroll
        for (int kt = 0; kt < 4; kt++) {
            u32 bv[4][2];
            #pragma unroll
            for (int dp = 0; dp < 2; dp++) {
                u32 off = (u32)((16 * kt + 8 * (g & 1) + lr) * 80 + (dp * 16 + 8 * (g >> 1)) * 2);
                ldsm4t(bv[2 * dp][0], bv[2 * dp][1], bv[2 * dp + 1][0], bv[2 * dp + 1][1], bV + off);
            }
            #pragma unroll
            for (int mi = 0; mi < 2; mi++) {
                u32 pa[4];
                pa[0] = packbf_rn(s[mi][2 * kt][0],     s[mi][2 * kt][1]);
                pa[1] = packbf_rn(s[mi][2 * kt][2],     s[mi][2 * kt][3]);
                pa[2] = packbf_rn(s[mi][2 * kt + 1][0], s[mi][2 * kt + 1][1]);
                pa[3] = packbf_rn(s[mi][2 * kt + 1][2], s[mi][2 * kt + 1][3]);
                #pragma unroll
                for (int dn = 0; dn < 4; dn++)
                    mma16816(o[mi][dn], pa, bv[dn]);
            }
        }

        if (t + 1 < NT) {
            const int nb = (t + 1) & 1;
            #pragma unroll
            for (int j = 0; j < 4; j++) {
                int o32 = skey[j] * ROWU + scol[j] * 2;
                float4 kf = kreg[j], vf = vreg[j];
                skhi[nb][o32]     = packbf_tr(kf.x, kf.y);
                skhi[nb][o32 + 1] = packbf_tr(kf.z, kf.w);
                sklo[nb][o32]     = packbf_rn(kf.x - trhi(kf.x), kf.y - trhi(kf.y));
                sklo[nb][o32 + 1] = packbf_rn(kf.z - trhi(kf.z), kf.w - trhi(kf.w));
                svv [nb][o32]     = packbf_rn(vf.x, vf.y);
                svv [nb][o32 + 1] = packbf_rn(vf.z, vf.w);
            }
        }
        __syncthreads();
    }

    #pragma unroll
    for (int mi = 0; mi < 2; mi++) {
        float inv0 = 1.0f / lrow[mi][0];
        float inv1 = 1.0f / lrow[mi][1];
        int r = qbase + mi * 16 + (lane >> 2);
        #pragma unroll
        for (int dn = 0; dn < 4; dn++) {
            int cc = h * HD + dn * 8 + 2 * (lane & 3);
            float2 o0 = {o[mi][dn][0] * inv0, o[mi][dn][1] * inv0};
            float2 o1 = {o[mi][dn][2] * inv1, o[mi][dn][3] * inv1};
            *reinterpret_cast<float2*>(xo + (size_t)r * CCH + cc)       = o0;
            *reinterpret_cast<float2*>(xo + (size_t)(r + 8) * CCH + cc) = o1;
        }
    }
}

// ---------------- [B*S, C] -> [B, C, S] output transpose -------------------
__global__ __launch_bounds__(256) void out_transpose_kernel(
    const float* __restrict__ src, float* __restrict__ dst)
{
    __shared__ float t[32][33];
    const int tx = threadIdx.x, ty = threadIdx.y;
    const int s0 = blockIdx.x * 32;
    const int c0 = blockIdx.y * 32;
    const int bb = blockIdx.z;
    #pragma unroll
    for (int i = ty; i < 32; i += 8)
        t[i][tx] = src[((size_t)bb * SEQ + s0 + i) * CCH + c0 + tx];
    __syncthreads();
    #pragma unroll
    for (int i = ty; i < 32; i += 8)
        dst[(size_t)bb * CCH * SEQ + (size_t)(c0 + i) * SEQ + s0 + tx] = t[tx][i];
}

// ---------------- launch ----------------------------------------------------
static float* sym(const void* symbol) {
    void* p = nullptr;
    cudaGetSymbolAddress(&p, symbol);
    return reinterpret_cast<float*>(p);
}

extern "C" void kernel_launch(void* const* d_in, const int* in_sizes, int n_in,
                              void* d_out, int out_size)
{
    const float* q = (const float*)d_in[0];
    const float* k = (const float*)d_in[1];
    const float* v = (const float*)d_in[2];
    const float* ln_g[3]  = {(const float*)d_in[3],  (const float*)d_in[9],  (const float*)d_in[15]};
    const float* ln_b[3]  = {(const float*)d_in[4],  (const float*)d_in[10], (const float*)d_in[16]};
    const float* w1[3]    = {(const float*)d_in[5],  (const float*)d_in[11], (const float*)d_in[17]};
    const float* b1[3]    = {(const float*)d_in[6],  (const float*)d_in[12], (const float*)d_in[18]};
    const float* w2[3]    = {(const float*)d_in[7],  (const float*)d_in[13], (const float*)d_in[19]};
    const float* b2[3]    = {(const float*)d_in[8],  (const float*)d_in[14], (const float*)d_in[20]};
    const float* m1_w1 = (const float*)d_in[21];
    const float* m1_b1 = (const float*)d_in[22];
    const float* m1_w2 = (const float*)d_in[23];
    const float* m1_b2 = (const float*)d_in[24];
    const float* m2_w1 = (const float*)d_in[25];
    const float* m2_b1 = (const float*)d_in[26];
    const float* m2_w2 = (const float*)d_in[27];
    const float* m2_b2 = (const float*)d_in[28];

    float* qp  = sym(g_qp);
    float* kp  = sym(g_kp);
    float* vp  = sym(g_vp);
    float* x   = sym(g_x);
    float* rs1 = sym(g_rs1);
    float* hb  = sym(g_h);

    const float* inp[3] = {q, k, v};
    float* prj[3] = {qp, kp, vp};

    dim3 g1(HID / 64, NTOK / 128);   // (4, 64)
    dim3 g2(CCH / 64, NTOK / 128);   // (2, 64)

    for (int p = 0; p < 3; p++) {
        ln_transpose_kernel<<<dim3(SEQ / 16, 2), 256>>>(inp[p], ln_g[p], ln_b[p], x);
        gemm_bf16_kernel<true,  false><<<g1, 128>>>(x,  w1[p], b1[p], nullptr, hb,     NTOK, CCH, HID);
        gemm_bf16_kernel<false, false><<<g2, 128>>>(hb, w2[p], b2[p], nullptr, prj[p], NTOK, HID, CCH);
    }

    attn_kernel<<<dim3(SEQ / 128, 2 * NH), 128>>>(qp, kp, vp, x);

    gemm_bf16_kernel<true,  false><<<g1, 128>>>(x,   m1_w1, m1_b1, nullptr, hb,  NTOK, CCH, HID);
    gemm_bf16_kernel<false, true ><<<g2, 128>>>(hb,  m1_w2, m1_b2, vp,      rs1, NTOK, HID, CCH);
    gemm_bf16_kernel<true,  false><<<g1, 128>>>(rs1, m2_w1, m2_b1, nullptr, hb,  NTOK, CCH, HID);
    gemm_bf16_kernel<false, true ><<<g2, 128>>>(hb,  m2_w2, m2_b2, rs1,     qp,  NTOK, HID, CCH);

    out_transpose_kernel<<<dim3(SEQ / 32, CCH / 32, 2), dim3(32, 8)>>>(qp, (float*)d_out);
}